// round 1
// baseline (speedup 1.0000x reference)
#include <cuda_runtime.h>
#include <math.h>

// LSTM cell fused kernel, fp32 SIMT baseline.
// gates[g] = x @ W[g]^T + pre_h @ U[g]^T   (g = i, f, o, n)
// c = sigmoid(f)*pre_c + sigmoid(i)*tanh(n);  h = sigmoid(o)*tanh(c)
// out = stack([h, c])  shape (2, 4096, 2048) fp32
//
// Tile: BM=128 batch rows x BU=32 units x 4 gates (=> 128x128 GEMM tile),
// BK=16, 256 threads, 64 fp32 accumulators per thread.

#define BM 128
#define BU 32
#define BJ 128   // 4 gates * BU
#define BK 16

#define NB    4096
#define NU    2048
#define NI    2048

__global__ __launch_bounds__(256, 1)
void lstm_fused_kernel(const float* __restrict__ pre_layer,  // [2, NB, NU]
                       const float* __restrict__ x,          // [NB, NI]
                       const float* __restrict__ W,          // [4, NU, NI]
                       const float* __restrict__ Umat,       // [4, NU, NU]
                       float* __restrict__ out)              // [2, NB, NU]
{
    __shared__ float As[BK][BM];
    __shared__ float Bs[BK][BJ];

    const int bm = blockIdx.y * BM;   // base batch row
    const int bu = blockIdx.x * BU;   // base unit (per gate)

    const int tid = threadIdx.x;
    const int tx  = tid & 15;         // 0..15
    const int ty  = tid >> 4;         // 0..15

    // acc[i][g*2+e]: i -> 8 m-rows (i<4: m=ty*4+i ; i>=4: m=64+ty*4+(i-4))
    //                g -> gate, e -> 2 unit cols (u = bu + tx*2 + e)
    float acc[8][8];
    #pragma unroll
    for (int i = 0; i < 8; i++)
        #pragma unroll
        for (int j = 0; j < 8; j++) acc[i][j] = 0.f;

    const float* pre_h = pre_layer;                       // [NB, NU]
    const float* pre_c = pre_layer + (size_t)NB * NU;     // [NB, NU]

    #pragma unroll 1
    for (int phase = 0; phase < 2; ++phase) {
        const float* Aptr  = (phase == 0) ? x : pre_h;    // [NB, 2048]
        const float* Bbase = (phase == 0) ? W : Umat;     // [4, NU, 2048]

        #pragma unroll 1
        for (int k0 = 0; k0 < 2048; k0 += BK) {
            __syncthreads();
            // ---- load A tile: BM x BK (row-major global, k contiguous) ----
            #pragma unroll
            for (int r = 0; r < 2; ++r) {
                int f4   = tid + r * 256;          // 0..511
                int row  = f4 >> 2;                // 0..127
                int col4 = (f4 & 3) * 4;           // 0,4,8,12
                float4 v = *reinterpret_cast<const float4*>(
                    &Aptr[(size_t)(bm + row) * 2048 + k0 + col4]);
                As[col4 + 0][row] = v.x;
                As[col4 + 1][row] = v.y;
                As[col4 + 2][row] = v.z;
                As[col4 + 3][row] = v.w;
            }
            // ---- load B tile: BJ x BK ; j = g*32 + ul ----
            #pragma unroll
            for (int r = 0; r < 2; ++r) {
                int f4   = tid + r * 256;
                int row  = f4 >> 2;                // j in 0..127
                int col4 = (f4 & 3) * 4;
                int g    = row >> 5;
                int ul   = row & 31;
                float4 v = *reinterpret_cast<const float4*>(
                    &Bbase[((size_t)g * NU + bu + ul) * 2048 + k0 + col4]);
                Bs[col4 + 0][row] = v.x;
                Bs[col4 + 1][row] = v.y;
                Bs[col4 + 2][row] = v.z;
                Bs[col4 + 3][row] = v.w;
            }
            __syncthreads();

            // ---- compute ----
            #pragma unroll
            for (int kk = 0; kk < BK; ++kk) {
                float a[8];
                float4 a0 = *reinterpret_cast<const float4*>(&As[kk][ty * 4]);
                float4 a1 = *reinterpret_cast<const float4*>(&As[kk][64 + ty * 4]);
                a[0]=a0.x; a[1]=a0.y; a[2]=a0.z; a[3]=a0.w;
                a[4]=a1.x; a[5]=a1.y; a[6]=a1.z; a[7]=a1.w;
                float b[8];
                #pragma unroll
                for (int g = 0; g < 4; ++g) {
                    float2 bv = *reinterpret_cast<const float2*>(&Bs[kk][g * 32 + tx * 2]);
                    b[g * 2 + 0] = bv.x;
                    b[g * 2 + 1] = bv.y;
                }
                #pragma unroll
                for (int i = 0; i < 8; ++i)
                    #pragma unroll
                    for (int j = 0; j < 8; ++j)
                        acc[i][j] = fmaf(a[i], b[j], acc[i][j]);
            }
        }
    }

    // ---- fused LSTM epilogue ----
    #pragma unroll
    for (int i = 0; i < 8; ++i) {
        int mloc = (i < 4) ? (ty * 4 + i) : (64 + ty * 4 + (i - 4));
        int m = bm + mloc;
        #pragma unroll
        for (int e = 0; e < 2; ++e) {
            int u = bu + tx * 2 + e;
            float gi = acc[i][0 * 2 + e];
            float gf = acc[i][1 * 2 + e];
            float go = acc[i][2 * 2 + e];
            float gn = acc[i][3 * 2 + e];

            float it = 1.f / (1.f + expf(-gi));
            float ft = 1.f / (1.f + expf(-gf));
            float ot = 1.f / (1.f + expf(-go));
            float nt = tanhf(gn);

            float pc = pre_c[(size_t)m * NU + u];
            float c  = ft * pc + it * nt;
            float h  = ot * tanhf(c);

            out[(size_t)m * NU + u]                   = h;
            out[(size_t)NB * NU + (size_t)m * NU + u] = c;
        }
    }
}

extern "C" void kernel_launch(void* const* d_in, const int* in_sizes, int n_in,
                              void* d_out, int out_size)
{
    const float* pre_layer = (const float*)d_in[0];  // (2, 4096, 2048)
    const float* x         = (const float*)d_in[1];  // (4096, 2048)
    const float* W         = (const float*)d_in[2];  // (4, 2048, 2048)
    const float* U         = (const float*)d_in[3];  // (4, 2048, 2048)
    float* out             = (float*)d_out;          // (2, 4096, 2048)

    dim3 grid(NU / BU, NB / BM);   // (64, 32) = 2048 CTAs
    dim3 block(256);
    lstm_fused_kernel<<<grid, block>>>(pre_layer, x, W, U, out);
}

// round 4
// speedup vs baseline: 2.0041x; 2.0041x over previous
#include <cuda_runtime.h>
#include <cuda_bf16.h>
#include <stdint.h>
#include <math.h>

// LSTM cell: gates = x@W^T + pre_h@U^T via mma.sync bf16 3-term split.
// N dim = 128 = 32 units x 4 gates, gate-minor (n = u*4 + g).
// Smem tiles use padded row stride (80 B) -> conflict-free ldmatrix, no swizzle.

#define NBATCH 4096
#define NUNITS 2048
#define KD     2048
#define BM 128
#define BK 32
#define NCH 128              // 2 phases * (2048/32)
#define RSTRIDE 80           // bytes per smem tile row (32 bf16 = 64B + 16B pad)
#define TILEB (128*RSTRIDE)  // 10240 B
#define STAGEB (4*TILEB)     // Ah, Al, Bh, Bl = 40960 B
#define SMEMB (3*STAGEB)     // 122880 B

// -------- bf16 hi/lo scratch --------
__device__ __align__(128) __nv_bfloat16 g_xh[(size_t)NBATCH*KD];
__device__ __align__(128) __nv_bfloat16 g_xl[(size_t)NBATCH*KD];
__device__ __align__(128) __nv_bfloat16 g_hh[(size_t)NBATCH*KD];
__device__ __align__(128) __nv_bfloat16 g_hl[(size_t)NBATCH*KD];
__device__ __align__(128) __nv_bfloat16 g_wh[(size_t)4*NUNITS*KD];
__device__ __align__(128) __nv_bfloat16 g_wl[(size_t)4*NUNITS*KD];
__device__ __align__(128) __nv_bfloat16 g_uh[(size_t)4*NUNITS*KD];
__device__ __align__(128) __nv_bfloat16 g_ul[(size_t)4*NUNITS*KD];

__device__ __forceinline__ uint32_t smem_u32(const void* p) {
    uint32_t a;
    asm("{ .reg .u64 t; cvta.to.shared.u64 t, %1; cvt.u32.u64 %0, t; }" : "=r"(a) : "l"(p));
    return a;
}
__device__ __forceinline__ void cp16(uint32_t dst, const void* src) {
    asm volatile("cp.async.cg.shared.global [%0], [%1], 16;" :: "r"(dst), "l"(src));
}
__device__ __forceinline__ void ldsm4(uint32_t& r0, uint32_t& r1, uint32_t& r2, uint32_t& r3,
                                      uint32_t addr) {
    asm volatile("ldmatrix.sync.aligned.m8n8.x4.shared.b16 {%0,%1,%2,%3}, [%4];"
                 : "=r"(r0), "=r"(r1), "=r"(r2), "=r"(r3) : "r"(addr));
}
__device__ __forceinline__ void mma16816(float* d, const uint32_t* a, const uint32_t* b) {
    asm volatile(
        "mma.sync.aligned.m16n8k16.row.col.f32.bf16.bf16.f32 "
        "{%0,%1,%2,%3}, {%4,%5,%6,%7}, {%8,%9}, {%0,%1,%2,%3};"
        : "+f"(d[0]), "+f"(d[1]), "+f"(d[2]), "+f"(d[3])
        : "r"(a[0]), "r"(a[1]), "r"(a[2]), "r"(a[3]), "r"(b[0]), "r"(b[1]));
}

// one chunk of cp.async: A_hi/A_lo/B_hi/B_lo tiles (128 rows x 32 bf16 each)
__device__ __forceinline__ void load_chunk(int c, uint32_t st, int bm, int bu, int tid) {
    const int koff = (c & 63) * BK;
    const __nv_bfloat16 *Ah, *Al, *Bh, *Bl;
    if (c < 64) { Ah = g_xh; Al = g_xl; Bh = g_wh; Bl = g_wl; }
    else        { Ah = g_hh; Al = g_hl; Bh = g_uh; Bl = g_ul; }
    #pragma unroll
    for (int i = 0; i < 2; ++i) {
        int e = i * 256 + tid;              // 512 16B units per tile
        int r = e >> 2, ch = e & 3;
        uint32_t d = st + r * RSTRIDE + ch * 16;
        size_t ga = (size_t)(bm + r) * KD + koff + ch * 8;
        cp16(d, Ah + ga);
        cp16(d + TILEB, Al + ga);
        int u = r >> 2, g = r & 3;          // B row r: n = u*4 + g (gate-minor)
        size_t gb = ((size_t)(g * NUNITS + bu + u)) * KD + koff + ch * 8;
        cp16(d + 2 * TILEB, Bh + gb);
        cp16(d + 3 * TILEB, Bl + gb);
    }
}

__global__ void __launch_bounds__(256, 1)
lstm_mma(const float* __restrict__ pre_c, float* __restrict__ out)
{
    extern __shared__ char smem[];
    const uint32_t sb = smem_u32(smem);
    const int tid = threadIdx.x, lane = tid & 31, wid = tid >> 5;
    const int bm = blockIdx.y * BM, bu = blockIdx.x * 32;
    const int wm = (wid >> 2) * 64, wn = (wid & 3) * 32;

    float acc[4][4][4];
    #pragma unroll
    for (int i = 0; i < 4; ++i)
        #pragma unroll
        for (int j = 0; j < 4; ++j)
            #pragma unroll
            for (int k = 0; k < 4; ++k) acc[i][j][k] = 0.f;

    load_chunk(0, sb, bm, bu, tid);
    asm volatile("cp.async.commit_group;" ::: "memory");
    load_chunk(1, sb + STAGEB, bm, bu, tid);
    asm volatile("cp.async.commit_group;" ::: "memory");

    // A frag addressing: row = wm + i*16 + (lane&15), chunk byte = (lane>>4)*16 + s*32
    const uint32_t aRow = (uint32_t)(lane & 15) * RSTRIDE + (uint32_t)(lane >> 4) * 16;
    // B frag addressing: row = wn + jj*16 + ((lane>>4)<<3) + (lane&7),
    //                    chunk byte = ((lane>>3)&1)*16 + s*32
    const uint32_t bRow = (uint32_t)(((lane >> 4) << 3) + (lane & 7)) * RSTRIDE
                        + (uint32_t)((lane >> 3) & 1) * 16;

    #pragma unroll 1
    for (int c = 0; c < NCH; ++c) {
        asm volatile("cp.async.wait_group 1;" ::: "memory");
        __syncthreads();
        if (c + 2 < NCH) {
            load_chunk(c + 2, sb + ((c + 2) % 3) * STAGEB, bm, bu, tid);
            asm volatile("cp.async.commit_group;" ::: "memory");
        } else {
            asm volatile("cp.async.commit_group;" ::: "memory");  // keep group count in step
        }

        const uint32_t stv = sb + (c % 3) * STAGEB;
        const uint32_t aH = stv + wm * RSTRIDE + aRow;
        const uint32_t aL = aH + TILEB;
        const uint32_t bH = stv + 2 * TILEB + wn * RSTRIDE + bRow;
        const uint32_t bL = bH + TILEB;

        #pragma unroll
        for (int s = 0; s < 2; ++s) {
            uint32_t ah[4][4], al[4][4], bh[4][2], bl[4][2];
            #pragma unroll
            for (int jj = 0; jj < 2; ++jj) {
                uint32_t off = jj * (16 * RSTRIDE) + s * 32;
                ldsm4(bh[2*jj][0], bh[2*jj][1], bh[2*jj+1][0], bh[2*jj+1][1], bH + off);
                ldsm4(bl[2*jj][0], bl[2*jj][1], bl[2*jj+1][0], bl[2*jj+1][1], bL + off);
            }
            #pragma unroll
            for (int i = 0; i < 4; ++i) {
                uint32_t off = i * (16 * RSTRIDE) + s * 32;
                ldsm4(ah[i][0], ah[i][1], ah[i][2], ah[i][3], aH + off);
                ldsm4(al[i][0], al[i][1], al[i][2], al[i][3], aL + off);
            }
            #pragma unroll
            for (int i = 0; i < 4; ++i)
                #pragma unroll
                for (int j = 0; j < 4; ++j) {
                    mma16816(acc[i][j], ah[i], bh[j]);
                    mma16816(acc[i][j], ah[i], bl[j]);
                    mma16816(acc[i][j], al[i], bh[j]);
                }
        }
    }

    // ---------------- epilogue: stage acc in smem, fuse LSTM ----------------
    __syncthreads();
    float* S = (float*)smem;                 // [8 warps][64 m][32 n-local]
    const uint32_t base = wid * 2048;
    #pragma unroll
    for (int i = 0; i < 4; ++i)
        #pragma unroll
        for (int j = 0; j < 4; ++j) {
            int r0 = i * 16 + (lane >> 2), c0 = j * 8 + (lane & 3) * 2;
            *(float2*)&S[base + r0 * 32 + c0]       = make_float2(acc[i][j][0], acc[i][j][1]);
            *(float2*)&S[base + (r0 + 8) * 32 + c0] = make_float2(acc[i][j][2], acc[i][j][3]);
        }
    __syncthreads();

    const size_t CO = (size_t)NBATCH * NUNITS;
    #pragma unroll
    for (int i = 0; i < 16; ++i) {
        int idx = i * 256 + tid;
        int m = idx >> 5, u = idx & 31;
        int wreg = (m >> 6) * 4 + (u >> 3);
        float4 gt = *(float4*)&S[wreg * 2048 + (m & 63) * 32 + (u & 7) * 4];
        float it = 1.f / (1.f + __expf(-gt.x));
        float ft = 1.f / (1.f + __expf(-gt.y));
        float ot = 1.f / (1.f + __expf(-gt.z));
        float nt = tanhf(gt.w);
        size_t o = (size_t)(bm + m) * NUNITS + bu + u;
        float cc = ft * pre_c[o] + it * nt;
        float hh = ot * tanhf(cc);
        out[o]      = hh;
        out[CO + o] = cc;
    }
}

// -------- fp32 -> bf16 hi/lo split --------
__global__ void split_bf16(const float* __restrict__ s,
                           __nv_bfloat16* __restrict__ hi,
                           __nv_bfloat16* __restrict__ lo, int n4)
{
    int i = blockIdx.x * 256 + threadIdx.x;
    if (i >= n4) return;
    float4 v = reinterpret_cast<const float4*>(s)[i];
    float f[4] = {v.x, v.y, v.z, v.w};
    unsigned short hs[4], ls[4];
    #pragma unroll
    for (int k = 0; k < 4; ++k) {
        __nv_bfloat16 h = __float2bfloat16(f[k]);
        __nv_bfloat16 l = __float2bfloat16(f[k] - __bfloat162float(h));
        hs[k] = *reinterpret_cast<unsigned short*>(&h);
        ls[k] = *reinterpret_cast<unsigned short*>(&l);
    }
    reinterpret_cast<ushort4*>(hi)[i] = make_ushort4(hs[0], hs[1], hs[2], hs[3]);
    reinterpret_cast<ushort4*>(lo)[i] = make_ushort4(ls[0], ls[1], ls[2], ls[3]);
}

extern "C" void kernel_launch(void* const* d_in, const int* in_sizes, int n_in,
                              void* d_out, int out_size)
{
    const float* pre_layer = (const float*)d_in[0];  // (2, 4096, 2048)
    const float* x         = (const float*)d_in[1];  // (4096, 2048)
    const float* W         = (const float*)d_in[2];  // (4, 2048, 2048)
    const float* U         = (const float*)d_in[3];  // (4, 2048, 2048)
    float* out             = (float*)d_out;

    void *pxh, *pxl, *phh, *phl, *pwh, *pwl, *puh, *pul;
    cudaGetSymbolAddress(&pxh, g_xh); cudaGetSymbolAddress(&pxl, g_xl);
    cudaGetSymbolAddress(&phh, g_hh); cudaGetSymbolAddress(&phl, g_hl);
    cudaGetSymbolAddress(&pwh, g_wh); cudaGetSymbolAddress(&pwl, g_wl);
    cudaGetSymbolAddress(&puh, g_uh); cudaGetSymbolAddress(&pul, g_ul);

    const int n4x = NBATCH * KD / 4;
    const int n4w = 4 * NUNITS * KD / 4;
    split_bf16<<<n4x / 256, 256>>>(x, (__nv_bfloat16*)pxh, (__nv_bfloat16*)pxl, n4x);
    split_bf16<<<n4x / 256, 256>>>(pre_layer, (__nv_bfloat16*)phh, (__nv_bfloat16*)phl, n4x);
    split_bf16<<<n4w / 256, 256>>>(W, (__nv_bfloat16*)pwh, (__nv_bfloat16*)pwl, n4w);
    split_bf16<<<n4w / 256, 256>>>(U, (__nv_bfloat16*)puh, (__nv_bfloat16*)pul, n4w);

    cudaFuncSetAttribute(lstm_mma, cudaFuncAttributeMaxDynamicSharedMemorySize, SMEMB);
    const float* pre_c = pre_layer + (size_t)NBATCH * NUNITS;
    lstm_mma<<<dim3(NUNITS / 32, NBATCH / BM), 256, SMEMB>>>(pre_c, out);
}

// round 5
// speedup vs baseline: 2.8547x; 1.4244x over previous
#include <cuda_runtime.h>
#include <cuda_bf16.h>
#include <stdint.h>
#include <math.h>

// LSTM cell: gates = x@W^T + pre_h@U^T via mma.sync bf16 3-term split.
// N = 128 = 32 units x 4 gates, gate-minor (n = u*4 + g).
// Smem tiles: 64B rows with XOR-16B-chunk swizzle (sel = (row>>1)&3), 3-stage
// cp.async pipeline, 2 CTAs/SM.

#define NBATCH 4096
#define NUNITS 2048
#define KD     2048
#define BM 128
#define BK 32
#define NCH 128               // 2 phases * (2048/32)
#define TILEB (128*64)        // 8192 B
#define STAGEB (4*TILEB)      // Ah, Al, Bh, Bl = 32768 B
#define SMEMB (3*STAGEB)      // 98304 B

// -------- bf16 hi/lo scratch --------
__device__ __align__(128) __nv_bfloat16 g_xh[(size_t)NBATCH*KD];
__device__ __align__(128) __nv_bfloat16 g_xl[(size_t)NBATCH*KD];
__device__ __align__(128) __nv_bfloat16 g_hh[(size_t)NBATCH*KD];
__device__ __align__(128) __nv_bfloat16 g_hl[(size_t)NBATCH*KD];
__device__ __align__(128) __nv_bfloat16 g_wh[(size_t)4*NUNITS*KD];
__device__ __align__(128) __nv_bfloat16 g_wl[(size_t)4*NUNITS*KD];
__device__ __align__(128) __nv_bfloat16 g_uh[(size_t)4*NUNITS*KD];
__device__ __align__(128) __nv_bfloat16 g_ul[(size_t)4*NUNITS*KD];

__device__ __forceinline__ uint32_t smem_u32(const void* p) {
    uint32_t a;
    asm("{ .reg .u64 t; cvta.to.shared.u64 t, %1; cvt.u32.u64 %0, t; }" : "=r"(a) : "l"(p));
    return a;
}
__device__ __forceinline__ void cp16(uint32_t dst, const void* src) {
    asm volatile("cp.async.cg.shared.global [%0], [%1], 16;" :: "r"(dst), "l"(src));
}
__device__ __forceinline__ void ldsm4(uint32_t& r0, uint32_t& r1, uint32_t& r2, uint32_t& r3,
                                      uint32_t addr) {
    asm volatile("ldmatrix.sync.aligned.m8n8.x4.shared.b16 {%0,%1,%2,%3}, [%4];"
                 : "=r"(r0), "=r"(r1), "=r"(r2), "=r"(r3) : "r"(addr));
}
__device__ __forceinline__ void mma16816(float* d, const uint32_t* a, const uint32_t* b) {
    asm volatile(
        "mma.sync.aligned.m16n8k16.row.col.f32.bf16.bf16.f32 "
        "{%0,%1,%2,%3}, {%4,%5,%6,%7}, {%8,%9}, {%0,%1,%2,%3};"
        : "+f"(d[0]), "+f"(d[1]), "+f"(d[2]), "+f"(d[3])
        : "r"(a[0]), "r"(a[1]), "r"(a[2]), "r"(a[3]), "r"(b[0]), "r"(b[1]));
}

// one chunk of cp.async: A_hi/A_lo/B_hi/B_lo tiles (128 rows x 32 bf16 each)
__device__ __forceinline__ void load_chunk(int c, uint32_t st, int bm, int bu, int tid) {
    const int koff = (c & 63) * BK;
    const __nv_bfloat16 *Ah, *Al, *Bh, *Bl;
    if (c < 64) { Ah = g_xh; Al = g_xl; Bh = g_wh; Bl = g_wl; }
    else        { Ah = g_hh; Al = g_hl; Bh = g_uh; Bl = g_ul; }
    #pragma unroll
    for (int i = 0; i < 2; ++i) {
        int e = i * 256 + tid;                 // 512 16B units per tile
        int r = e >> 2, ch = e & 3;
        uint32_t d = st + r * 64 + (((ch ^ ((r >> 1) & 3))) << 4);
        size_t ga = (size_t)(bm + r) * KD + koff + ch * 8;
        cp16(d, Ah + ga);
        cp16(d + TILEB, Al + ga);
        int u = r >> 2, g = r & 3;             // B row r: n = u*4 + g (gate-minor)
        size_t gb = ((size_t)(g * NUNITS + bu + u)) * KD + koff + ch * 8;
        cp16(d + 2 * TILEB, Bh + gb);
        cp16(d + 3 * TILEB, Bl + gb);
    }
}

__global__ void __launch_bounds__(256, 2)
lstm_mma(const float* __restrict__ pre_c, float* __restrict__ out)
{
    extern __shared__ char smem[];
    const uint32_t sb = smem_u32(smem);
    const int tid = threadIdx.x, lane = tid & 31, wid = tid >> 5;
    const int bm = blockIdx.y * BM, bu = blockIdx.x * 32;
    const int wm = (wid >> 2) * 64, wn = (wid & 3) * 32;

    float acc[4][4][4];
    #pragma unroll
    for (int i = 0; i < 4; ++i)
        #pragma unroll
        for (int j = 0; j < 4; ++j)
            #pragma unroll
            for (int k = 0; k < 4; ++k) acc[i][j][k] = 0.f;

    load_chunk(0, sb, bm, bu, tid);
    asm volatile("cp.async.commit_group;" ::: "memory");
    load_chunk(1, sb + STAGEB, bm, bu, tid);
    asm volatile("cp.async.commit_group;" ::: "memory");

    // A frag: row = wm + i*16 + (lane&15); logical 16B chunk ch = (lane>>4) + 2s
    const int rA = wm + (lane & 15);
    const uint32_t aBase = (uint32_t)rA * 64;
    const int selA = (rA >> 1) & 3;
    const int chA0 = lane >> 4;
    // B frag: row = wn + jj*16 + ((lane>>4)<<3) + (lane&7); ch = ((lane>>3)&1) + 2s
    const int rB = wn + (((lane >> 4) << 3) + (lane & 7));
    const uint32_t bBase = (uint32_t)rB * 64;
    const int selB = (rB >> 1) & 3;
    const int chB0 = (lane >> 3) & 1;

    #pragma unroll 1
    for (int c = 0; c < NCH; ++c) {
        __syncthreads();                              // all done computing c-1
        if (c + 2 < NCH) {
            load_chunk(c + 2, sb + ((c + 2) % 3) * STAGEB, bm, bu, tid);
        }
        asm volatile("cp.async.commit_group;" ::: "memory");
        asm volatile("cp.async.wait_group 2;" ::: "memory");  // chunk c's loads done
        __syncthreads();

        const uint32_t stv = sb + (c % 3) * STAGEB;
        const uint32_t aH = stv + aBase;
        const uint32_t bH = stv + 2 * TILEB + bBase;

        #pragma unroll
        for (int s = 0; s < 2; ++s) {
            const uint32_t offB = (uint32_t)(((chB0 + 2 * s) ^ selB) << 4);
            const uint32_t offA = (uint32_t)(((chA0 + 2 * s) ^ selA) << 4);
            uint32_t bh[4][2], bl[4][2];
            #pragma unroll
            for (int jj = 0; jj < 2; ++jj) {
                uint32_t ad = bH + jj * 1024 + offB;
                ldsm4(bh[2*jj][0], bh[2*jj][1], bh[2*jj+1][0], bh[2*jj+1][1], ad);
                ldsm4(bl[2*jj][0], bl[2*jj][1], bl[2*jj+1][0], bl[2*jj+1][1], ad + TILEB);
            }
            #pragma unroll
            for (int i = 0; i < 4; ++i) {
                uint32_t ah[4], al[4];
                uint32_t ad = aH + i * 1024 + offA;
                ldsm4(ah[0], ah[1], ah[2], ah[3], ad);
                ldsm4(al[0], al[1], al[2], al[3], ad + TILEB);
                #pragma unroll
                for (int j = 0; j < 4; ++j) {
                    mma16816(acc[i][j], ah, bh[j]);
                    mma16816(acc[i][j], ah, bl[j]);
                    mma16816(acc[i][j], al, bh[j]);
                }
            }
        }
    }

    // ---------------- epilogue: stage acc in smem, fuse LSTM ----------------
    __syncthreads();
    float* S = (float*)smem;                 // [8 warps][64 m][32 n-local]
    const uint32_t base = wid * 2048;
    #pragma unroll
    for (int i = 0; i < 4; ++i)
        #pragma unroll
        for (int j = 0; j < 4; ++j) {
            int r0 = i * 16 + (lane >> 2), c0 = j * 8 + (lane & 3) * 2;
            *(float2*)&S[base + r0 * 32 + c0]       = make_float2(acc[i][j][0], acc[i][j][1]);
            *(float2*)&S[base + (r0 + 8) * 32 + c0] = make_float2(acc[i][j][2], acc[i][j][3]);
        }
    __syncthreads();

    const size_t CO = (size_t)NBATCH * NUNITS;
    #pragma unroll
    for (int i = 0; i < 16; ++i) {
        int idx = i * 256 + tid;
        int m = idx >> 5, u = idx & 31;
        int wreg = (m >> 6) * 4 + (u >> 3);
        float4 gt = *(float4*)&S[wreg * 2048 + (m & 63) * 32 + (u & 7) * 4];
        float it = 1.f / (1.f + __expf(-gt.x));
        float ft = 1.f / (1.f + __expf(-gt.y));
        float ot = 1.f / (1.f + __expf(-gt.z));
        float nt = tanhf(gt.w);
        size_t o = (size_t)(bm + m) * NUNITS + bu + u;
        float cc = ft * pre_c[o] + it * nt;
        float hh = ot * tanhf(cc);
        out[o]      = hh;
        out[CO + o] = cc;
    }
}

// -------- fp32 -> bf16 hi/lo split --------
__global__ void split_bf16(const float* __restrict__ s,
                           __nv_bfloat16* __restrict__ hi,
                           __nv_bfloat16* __restrict__ lo, int n4)
{
    int i = blockIdx.x * 256 + threadIdx.x;
    if (i >= n4) return;
    float4 v = reinterpret_cast<const float4*>(s)[i];
    float f[4] = {v.x, v.y, v.z, v.w};
    unsigned short hs[4], ls[4];
    #pragma unroll
    for (int k = 0; k < 4; ++k) {
        __nv_bfloat16 h = __float2bfloat16(f[k]);
        __nv_bfloat16 l = __float2bfloat16(f[k] - __bfloat162float(h));
        hs[k] = *reinterpret_cast<unsigned short*>(&h);
        ls[k] = *reinterpret_cast<unsigned short*>(&l);
    }
    reinterpret_cast<ushort4*>(hi)[i] = make_ushort4(hs[0], hs[1], hs[2], hs[3]);
    reinterpret_cast<ushort4*>(lo)[i] = make_ushort4(ls[0], ls[1], ls[2], ls[3]);
}

extern "C" void kernel_launch(void* const* d_in, const int* in_sizes, int n_in,
                              void* d_out, int out_size)
{
    const float* pre_layer = (const float*)d_in[0];  // (2, 4096, 2048)
    const float* x         = (const float*)d_in[1];  // (4096, 2048)
    const float* W         = (const float*)d_in[2];  // (4, 2048, 2048)
    const float* U         = (const float*)d_in[3];  // (4, 2048, 2048)
    float* out             = (float*)d_out;

    void *pxh, *pxl, *phh, *phl, *pwh, *pwl, *puh, *pul;
    cudaGetSymbolAddress(&pxh, g_xh); cudaGetSymbolAddress(&pxl, g_xl);
    cudaGetSymbolAddress(&phh, g_hh); cudaGetSymbolAddress(&phl, g_hl);
    cudaGetSymbolAddress(&pwh, g_wh); cudaGetSymbolAddress(&pwl, g_wl);
    cudaGetSymbolAddress(&puh, g_uh); cudaGetSymbolAddress(&pul, g_ul);

    const int n4x = NBATCH * KD / 4;
    const int n4w = 4 * NUNITS * KD / 4;
    split_bf16<<<n4x / 256, 256>>>(x, (__nv_bfloat16*)pxh, (__nv_bfloat16*)pxl, n4x);
    split_bf16<<<n4x / 256, 256>>>(pre_layer, (__nv_bfloat16*)phh, (__nv_bfloat16*)phl, n4x);
    split_bf16<<<n4w / 256, 256>>>(W, (__nv_bfloat16*)pwh, (__nv_bfloat16*)pwl, n4w);
    split_bf16<<<n4w / 256, 256>>>(U, (__nv_bfloat16*)puh, (__nv_bfloat16*)pul, n4w);

    cudaFuncSetAttribute(lstm_mma, cudaFuncAttributeMaxDynamicSharedMemorySize, SMEMB);
    const float* pre_c = pre_layer + (size_t)NBATCH * NUNITS;
    lstm_mma<<<dim3(NUNITS / 32, NBATCH / BM), 256, SMEMB>>>(pre_c, out);
}

// round 6
// speedup vs baseline: 2.8634x; 1.0031x over previous
#include <cuda_runtime.h>
#include <cuda_bf16.h>
#include <stdint.h>
#include <math.h>

// LSTM cell: gates = x@W^T + pre_h@U^T via mma.sync bf16 3-term split.
// N = 128 = 32 units x 4 gates, gate-minor (n = u*4 + g).
// 3-stage cp.async pipeline, ONE __syncthreads per chunk, 2 CTAs/SM.

#define NBATCH 4096
#define NUNITS 2048
#define KD     2048
#define BM 128
#define BK 32
#define NCH 128               // 2 phases * (2048/32)
#define TILEB (128*64)        // 8192 B
#define STAGEB (4*TILEB)      // Ah, Al, Bh, Bl = 32768 B
#define SMEMB (3*STAGEB)      // 98304 B

// -------- bf16 hi/lo scratch --------
__device__ __align__(128) __nv_bfloat16 g_xh[(size_t)NBATCH*KD];
__device__ __align__(128) __nv_bfloat16 g_xl[(size_t)NBATCH*KD];
__device__ __align__(128) __nv_bfloat16 g_hh[(size_t)NBATCH*KD];
__device__ __align__(128) __nv_bfloat16 g_hl[(size_t)NBATCH*KD];
__device__ __align__(128) __nv_bfloat16 g_wh[(size_t)4*NUNITS*KD];
__device__ __align__(128) __nv_bfloat16 g_wl[(size_t)4*NUNITS*KD];
__device__ __align__(128) __nv_bfloat16 g_uh[(size_t)4*NUNITS*KD];
__device__ __align__(128) __nv_bfloat16 g_ul[(size_t)4*NUNITS*KD];

__device__ __forceinline__ uint32_t smem_u32(const void* p) {
    uint32_t a;
    asm("{ .reg .u64 t; cvta.to.shared.u64 t, %1; cvt.u32.u64 %0, t; }" : "=r"(a) : "l"(p));
    return a;
}
__device__ __forceinline__ void cp16(uint32_t dst, const void* src) {
    asm volatile("cp.async.cg.shared.global [%0], [%1], 16;" :: "r"(dst), "l"(src));
}
__device__ __forceinline__ void ldsm4(uint32_t& r0, uint32_t& r1, uint32_t& r2, uint32_t& r3,
                                      uint32_t addr) {
    asm volatile("ldmatrix.sync.aligned.m8n8.x4.shared.b16 {%0,%1,%2,%3}, [%4];"
                 : "=r"(r0), "=r"(r1), "=r"(r2), "=r"(r3) : "r"(addr));
}
__device__ __forceinline__ void mma16816(float* d, const uint32_t* a, const uint32_t* b) {
    asm volatile(
        "mma.sync.aligned.m16n8k16.row.col.f32.bf16.bf16.f32 "
        "{%0,%1,%2,%3}, {%4,%5,%6,%7}, {%8,%9}, {%0,%1,%2,%3};"
        : "+f"(d[0]), "+f"(d[1]), "+f"(d[2]), "+f"(d[3])
        : "r"(a[0]), "r"(a[1]), "r"(a[2]), "r"(a[3]), "r"(b[0]), "r"(b[1]));
}

// one chunk of cp.async: A_hi/A_lo/B_hi/B_lo tiles (128 rows x 32 bf16 each)
__device__ __forceinline__ void load_chunk(int c, uint32_t st, int bm, int bu, int tid) {
    const int koff = (c & 63) * BK;
    const __nv_bfloat16 *Ah, *Al, *Bh, *Bl;
    if (c < 64) { Ah = g_xh; Al = g_xl; Bh = g_wh; Bl = g_wl; }
    else        { Ah = g_hh; Al = g_hl; Bh = g_uh; Bl = g_ul; }
    #pragma unroll
    for (int i = 0; i < 2; ++i) {
        int e = i * 256 + tid;                 // 512 16B units per tile
        int r = e >> 2, ch = e & 3;
        uint32_t d = st + r * 64 + (((ch ^ ((r >> 1) & 3))) << 4);
        size_t ga = (size_t)(bm + r) * KD + koff + ch * 8;
        cp16(d, Ah + ga);
        cp16(d + TILEB, Al + ga);
        int u = r >> 2, g = r & 3;             // B row r: n = u*4 + g (gate-minor)
        size_t gb = ((size_t)(g * NUNITS + bu + u)) * KD + koff + ch * 8;
        cp16(d + 2 * TILEB, Bh + gb);
        cp16(d + 3 * TILEB, Bl + gb);
    }
}

__global__ void __launch_bounds__(256, 2)
lstm_mma(const float* __restrict__ pre_c, float* __restrict__ out)
{
    extern __shared__ char smem[];
    const uint32_t sb = smem_u32(smem);
    const int tid = threadIdx.x, lane = tid & 31, wid = tid >> 5;
    const int bm = blockIdx.y * BM, bu = blockIdx.x * 32;
    const int wm = (wid >> 2) * 64, wn = (wid & 3) * 32;

    float acc[4][4][4];
    #pragma unroll
    for (int i = 0; i < 4; ++i)
        #pragma unroll
        for (int j = 0; j < 4; ++j)
            #pragma unroll
            for (int k = 0; k < 4; ++k) acc[i][j][k] = 0.f;

    load_chunk(0, sb, bm, bu, tid);
    asm volatile("cp.async.commit_group;" ::: "memory");
    load_chunk(1, sb + STAGEB, bm, bu, tid);
    asm volatile("cp.async.commit_group;" ::: "memory");

    // A frag: row = wm + i*16 + (lane&15); logical 16B chunk ch = (lane>>4) + 2s
    const int rA = wm + (lane & 15);
    const uint32_t aBase = (uint32_t)rA * 64;
    const int selA = (rA >> 1) & 3;
    const int chA0 = lane >> 4;
    // B frag: row = wn + jj*16 + ((lane>>4)<<3) + (lane&7); ch = ((lane>>3)&1) + 2s
    const int rB = wn + (((lane >> 4) << 3) + (lane & 7));
    const uint32_t bBase = (uint32_t)rB * 64;
    const int selB = (rB >> 1) & 3;
    const int chB0 = (lane >> 3) & 1;

    uint32_t stv  = sb;                  // stage holding chunk c
    uint32_t stn  = sb + STAGEB;         // chunk c+1
    uint32_t stn2 = sb + 2 * STAGEB;     // chunk c+2 (to be filled)

    #pragma unroll 1
    for (int c = 0; c < NCH; ++c) {
        asm volatile("cp.async.wait_group 1;" ::: "memory");  // chunk c resident
        __syncthreads();   // data visible to all; all warps done with buffer stn2's old chunk
        if (c + 2 < NCH) load_chunk(c + 2, stn2, bm, bu, tid);
        asm volatile("cp.async.commit_group;" ::: "memory");

        const uint32_t aH = stv + aBase;
        const uint32_t bH = stv + 2 * TILEB + bBase;

        #pragma unroll
        for (int s = 0; s < 2; ++s) {
            const uint32_t offB = (uint32_t)(((chB0 + 2 * s) ^ selB) << 4);
            const uint32_t offA = (uint32_t)(((chA0 + 2 * s) ^ selA) << 4);
            uint32_t bh[4][2], bl[4][2];
            #pragma unroll
            for (int jj = 0; jj < 2; ++jj) {
                uint32_t ad = bH + jj * 1024 + offB;
                ldsm4(bh[2*jj][0], bh[2*jj][1], bh[2*jj+1][0], bh[2*jj+1][1], ad);
                ldsm4(bl[2*jj][0], bl[2*jj][1], bl[2*jj+1][0], bl[2*jj+1][1], ad + TILEB);
            }
            #pragma unroll
            for (int i = 0; i < 4; ++i) {
                uint32_t ah[4], al[4];
                uint32_t ad = aH + i * 1024 + offA;
                ldsm4(ah[0], ah[1], ah[2], ah[3], ad);
                ldsm4(al[0], al[1], al[2], al[3], ad + TILEB);
                #pragma unroll
                for (int j = 0; j < 4; ++j) {
                    mma16816(acc[i][j], ah, bh[j]);
                    mma16816(acc[i][j], ah, bl[j]);
                    mma16816(acc[i][j], al, bh[j]);
                }
            }
        }
        uint32_t t = stv; stv = stn; stn = stn2; stn2 = t;   // rotate stages
    }

    // ---------------- epilogue: stage acc in smem, fuse LSTM ----------------
    __syncthreads();
    float* S = (float*)smem;                 // [8 warps][64 m][32 n-local]
    const uint32_t base = wid * 2048;
    #pragma unroll
    for (int i = 0; i < 4; ++i)
        #pragma unroll
        for (int j = 0; j < 4; ++j) {
            int r0 = i * 16 + (lane >> 2), c0 = j * 8 + (lane & 3) * 2;
            *(float2*)&S[base + r0 * 32 + c0]       = make_float2(acc[i][j][0], acc[i][j][1]);
            *(float2*)&S[base + (r0 + 8) * 32 + c0] = make_float2(acc[i][j][2], acc[i][j][3]);
        }
    __syncthreads();

    const size_t CO = (size_t)NBATCH * NUNITS;
    #pragma unroll
    for (int i = 0; i < 16; ++i) {
        int idx = i * 256 + tid;
        int m = idx >> 5, u = idx & 31;
        int wreg = (m >> 6) * 4 + (u >> 3);
        float4 gt = *(float4*)&S[wreg * 2048 + (m & 63) * 32 + (u & 7) * 4];
        float it = 1.f / (1.f + __expf(-gt.x));
        float ft = 1.f / (1.f + __expf(-gt.y));
        float ot = 1.f / (1.f + __expf(-gt.z));
        float nt = tanhf(gt.w);
        size_t o = (size_t)(bm + m) * NUNITS + bu + u;
        float cc = ft * pre_c[o] + it * nt;
        float hh = ot * tanhf(cc);
        out[o]      = hh;
        out[CO + o] = cc;
    }
}

// -------- fp32 -> bf16 hi/lo split, all 4 tensors in one launch --------
// segments (in float4 units): x: [0, 2M), pre_layer(h): [2M, 4M),
// W: [4M, 8M), U: [8M, 12M)   where M = 1<<20
__global__ void split_all(const float* __restrict__ x, const float* __restrict__ ph,
                          const float* __restrict__ W, const float* __restrict__ U)
{
    const int SEG = NBATCH * KD / 4;               // 2M float4 per x-like tensor
    int i = blockIdx.x * 256 + threadIdx.x;
    const float* s; __nv_bfloat16 *hi, *lo; int off;
    if (i < SEG)            { s = x;  hi = g_xh; lo = g_xl; off = i; }
    else if (i < 2 * SEG)   { s = ph; hi = g_hh; lo = g_hl; off = i - SEG; }
    else if (i < 4 * SEG)   { s = W;  hi = g_wh; lo = g_wl; off = i - 2 * SEG; }
    else                    { s = U;  hi = g_uh; lo = g_ul; off = i - 4 * SEG; }
    float4 v = reinterpret_cast<const float4*>(s)[off];
    float f[4] = {v.x, v.y, v.z, v.w};
    unsigned short hs[4], ls[4];
    #pragma unroll
    for (int k = 0; k < 4; ++k) {
        __nv_bfloat16 h = __float2bfloat16(f[k]);
        __nv_bfloat16 l = __float2bfloat16(f[k] - __bfloat162float(h));
        hs[k] = *reinterpret_cast<unsigned short*>(&h);
        ls[k] = *reinterpret_cast<unsigned short*>(&l);
    }
    reinterpret_cast<ushort4*>(hi)[off] = make_ushort4(hs[0], hs[1], hs[2], hs[3]);
    reinterpret_cast<ushort4*>(lo)[off] = make_ushort4(ls[0], ls[1], ls[2], ls[3]);
}

extern "C" void kernel_launch(void* const* d_in, const int* in_sizes, int n_in,
                              void* d_out, int out_size)
{
    const float* pre_layer = (const float*)d_in[0];  // (2, 4096, 2048)
    const float* x         = (const float*)d_in[1];  // (4096, 2048)
    const float* W         = (const float*)d_in[2];  // (4, 2048, 2048)
    const float* U         = (const float*)d_in[3];  // (4, 2048, 2048)
    float* out             = (float*)d_out;

    const int SEG = NBATCH * KD / 4;                 // 2M
    const int total = 6 * SEG;                       // x + h + 2*(W) + 2*(U) segments? (x,h,W,U = 1+1+2+2)
    split_all<<<total / 256, 256>>>(x, pre_layer, W, U);

    cudaFuncSetAttribute(lstm_mma, cudaFuncAttributeMaxDynamicSharedMemorySize, SMEMB);
    const float* pre_c = pre_layer + (size_t)NBATCH * NUNITS;
    lstm_mma<<<dim3(NUNITS / 32, NBATCH / BM), 256, SMEMB>>>(pre_c, out);
}